// round 1
// baseline (speedup 1.0000x reference)
#include <cuda_runtime.h>

// VecInt: scaling-and-squaring integration of a stationary velocity field.
// vec (1,3,160,192,160) fp32, nsteps=7 (fixed by setup_inputs).
//
// Strategy:
//  - Convert SoA -> AoS float4 scratch (displacement pre-scaled to VOXEL units,
//    i.e. multiplied by (dim-1)/2 per channel) so each trilinear corner is a
//    single aligned LDG.128 and sample position is simply p + v.
//  - 7 ping-pong integration passes: out[p] = in[p] + trilerp(in, p + in[p]).
//  - Convert back AoS -> SoA with the inverse per-channel scale.

constexpr int D = 160;
constexpr int H = 192;
constexpr int W = 160;
constexpr int NVOX = D * H * W;          // 4,915,200
constexpr int NSTEPS = 7;

// ping-pong scratch (AoS, 16B/voxel) — static device arrays (no allocation)
__device__ float4 g_bufA[NVOX];
__device__ float4 g_bufB[NVOX];

// half-extents per axis (z,y,x) for normalized<->voxel conversion
__device__ __forceinline__ float hext_z() { return 0.5f * (D - 1); } // 79.5
__device__ __forceinline__ float hext_y() { return 0.5f * (H - 1); } // 95.5
__device__ __forceinline__ float hext_x() { return 0.5f * (W - 1); } // 79.5

__global__ void __launch_bounds__(256)
scale_in_kernel(const float* __restrict__ in, float4* __restrict__ out)
{
    int idx = blockIdx.x * 256 + threadIdx.x;
    if (idx >= NVOX) return;
    const float s = 1.0f / 128.0f;   // 1/2^7
    float4 r;
    r.x = in[idx]            * (s * 0.5f * (D - 1));
    r.y = in[idx + NVOX]     * (s * 0.5f * (H - 1));
    r.z = in[idx + 2 * NVOX] * (s * 0.5f * (W - 1));
    r.w = 0.0f;
    out[idx] = r;
}

__global__ void __launch_bounds__(256)
integrate_kernel(const float4* __restrict__ in, float4* __restrict__ out)
{
    int idx = blockIdx.x * 256 + threadIdx.x;
    if (idx >= NVOX) return;

    int x = idx % W;
    int t = idx / W;
    int y = t % H;
    int z = t / H;

    float4 v = in[idx];

    // sample position in voxel units
    float zf = (float)z + v.x;
    float yf = (float)y + v.y;
    float xf = (float)x + v.z;

    float z0f = floorf(zf), y0f = floorf(yf), x0f = floorf(xf);
    float fz = zf - z0f, fy = yf - y0f, fx = xf - x0f;
    int z0 = (int)z0f, y0 = (int)y0f, x0 = (int)x0f;
    int z1 = z0 + 1, y1 = y0 + 1, x1 = x0 + 1;

    // per-axis weights with validity folded in (zero weight if index OOB
    // == border-zero padding of the reference)
    float Wz0 = ((unsigned)z0 < (unsigned)D) ? (1.0f - fz) : 0.0f;
    float Wz1 = ((unsigned)z1 < (unsigned)D) ? fz          : 0.0f;
    float Wy0 = ((unsigned)y0 < (unsigned)H) ? (1.0f - fy) : 0.0f;
    float Wy1 = ((unsigned)y1 < (unsigned)H) ? fy          : 0.0f;
    float Wx0 = ((unsigned)x0 < (unsigned)W) ? (1.0f - fx) : 0.0f;
    float Wx1 = ((unsigned)x1 < (unsigned)W) ? fx          : 0.0f;

    // clamped indices (safe loads; contribution zeroed by weights when OOB)
    int zc0 = min(max(z0, 0), D - 1), zc1 = min(max(z1, 0), D - 1);
    int yc0 = min(max(y0, 0), H - 1), yc1 = min(max(y1, 0), H - 1);
    int xc0 = min(max(x0, 0), W - 1), xc1 = min(max(x1, 0), W - 1);

    int r00 = (zc0 * H + yc0) * W;
    int r01 = (zc0 * H + yc1) * W;
    int r10 = (zc1 * H + yc0) * W;
    int r11 = (zc1 * H + yc1) * W;

    // 8 corner gathers, one LDG.128 each, all independent (MLP=8)
    float4 c000 = in[r00 + xc0];
    float4 c001 = in[r00 + xc1];
    float4 c010 = in[r01 + xc0];
    float4 c011 = in[r01 + xc1];
    float4 c100 = in[r10 + xc0];
    float4 c101 = in[r10 + xc1];
    float4 c110 = in[r11 + xc0];
    float4 c111 = in[r11 + xc1];

    // trilinear blend per channel
    float sx, sy, sz;
    {
        float a00 = fmaf(c001.x, Wx1, c000.x * Wx0);
        float a01 = fmaf(c011.x, Wx1, c010.x * Wx0);
        float a10 = fmaf(c101.x, Wx1, c100.x * Wx0);
        float a11 = fmaf(c111.x, Wx1, c110.x * Wx0);
        float b0  = fmaf(a01, Wy1, a00 * Wy0);
        float b1  = fmaf(a11, Wy1, a10 * Wy0);
        sx = fmaf(b1, Wz1, b0 * Wz0);
    }
    {
        float a00 = fmaf(c001.y, Wx1, c000.y * Wx0);
        float a01 = fmaf(c011.y, Wx1, c010.y * Wx0);
        float a10 = fmaf(c101.y, Wx1, c100.y * Wx0);
        float a11 = fmaf(c111.y, Wx1, c110.y * Wx0);
        float b0  = fmaf(a01, Wy1, a00 * Wy0);
        float b1  = fmaf(a11, Wy1, a10 * Wy0);
        sy = fmaf(b1, Wz1, b0 * Wz0);
    }
    {
        float a00 = fmaf(c001.z, Wx1, c000.z * Wx0);
        float a01 = fmaf(c011.z, Wx1, c010.z * Wx0);
        float a10 = fmaf(c101.z, Wx1, c100.z * Wx0);
        float a11 = fmaf(c111.z, Wx1, c110.z * Wx0);
        float b0  = fmaf(a01, Wy1, a00 * Wy0);
        float b1  = fmaf(a11, Wy1, a10 * Wy0);
        sz = fmaf(b1, Wz1, b0 * Wz0);
    }

    float4 r;
    r.x = v.x + sx;
    r.y = v.y + sy;
    r.z = v.z + sz;
    r.w = 0.0f;
    out[idx] = r;
}

__global__ void __launch_bounds__(256)
scale_out_kernel(const float4* __restrict__ in, float* __restrict__ out)
{
    int idx = blockIdx.x * 256 + threadIdx.x;
    if (idx >= NVOX) return;
    float4 v = in[idx];
    out[idx]            = v.x * (1.0f / (0.5f * (D - 1)));
    out[idx + NVOX]     = v.y * (1.0f / (0.5f * (H - 1)));
    out[idx + 2 * NVOX] = v.z * (1.0f / (0.5f * (W - 1)));
}

extern "C" void kernel_launch(void* const* d_in, const int* in_sizes, int n_in,
                              void* d_out, int out_size)
{
    const float* vec = (const float*)d_in[0];
    float* out = (float*)d_out;

    float4 *bufA, *bufB;
    cudaGetSymbolAddress((void**)&bufA, g_bufA);
    cudaGetSymbolAddress((void**)&bufB, g_bufB);

    const int threads = 256;
    const int blocks = (NVOX + threads - 1) / threads;

    scale_in_kernel<<<blocks, threads>>>(vec, bufA);

    float4* cur = bufA;
    float4* nxt = bufB;
    for (int i = 0; i < NSTEPS; ++i) {
        integrate_kernel<<<blocks, threads>>>(cur, nxt);
        float4* tmp = cur; cur = nxt; nxt = tmp;
    }

    scale_out_kernel<<<blocks, threads>>>(cur, out);
}

// round 2
// speedup vs baseline: 1.1820x; 1.1820x over previous
#include <cuda_runtime.h>

// VecInt: scaling-and-squaring integration of a stationary velocity field.
// vec (1,3,160,192,160) fp32, nsteps=7.
//
// Round 2: pair-lane gather. Two lanes cooperate on one voxel — even lane
// gathers the x0 column of the trilinear cube, odd lane gathers x1. The
// x-adjacent corner pair (32 contiguous bytes) now lands in ONE load
// instruction across adjacent lanes, so the L1tex coalescer serves it with a
// single 128B-line wavefront instead of two. Gather instructions/voxel: 8->4,
// L1 wavefronts/voxel ~8.25 -> ~4.75. Final pass fused with SoA scale-out.

constexpr int D = 160;
constexpr int H = 192;
constexpr int W = 160;
constexpr int NVOX = D * H * W;          // 4,915,200 (divisible by 128)
constexpr int NSTEPS = 7;

__device__ float4 g_bufA[NVOX];
__device__ float4 g_bufB[NVOX];

__global__ void __launch_bounds__(256)
scale_in_kernel(const float* __restrict__ in, float4* __restrict__ out)
{
    int idx = blockIdx.x * 256 + threadIdx.x;
    const float s = 1.0f / 128.0f;   // 1/2^7
    float4 r;
    r.x = in[idx]            * (s * 0.5f * (D - 1));
    r.y = in[idx + NVOX]     * (s * 0.5f * (H - 1));
    r.z = in[idx + 2 * NVOX] * (s * 0.5f * (W - 1));
    r.w = 0.0f;
    out[idx] = r;
}

// 2 lanes per voxel. sub==0 lane handles x0 corners, sub==1 lane handles x1.
template<bool LAST>
__global__ void __launch_bounds__(256)
integrate_kernel(const float4* __restrict__ in, float4* __restrict__ out4,
                 float* __restrict__ out_soa)
{
    int t   = blockIdx.x * 256 + threadIdx.x;
    int idx = t >> 1;
    int sub = t & 1;

    int x = idx % W;
    int tt = idx / W;
    int y = tt % H;
    int z = tt / H;

    float4 v = in[idx];   // same address in both pair lanes -> broadcast

    float zf = (float)z + v.x;
    float yf = (float)y + v.y;
    float xf = (float)x + v.z;

    float z0f = floorf(zf), y0f = floorf(yf), x0f = floorf(xf);
    float fz = zf - z0f, fy = yf - y0f, fx = xf - x0f;
    int z0 = (int)z0f, y0 = (int)y0f, x0 = (int)x0f;
    int z1 = z0 + 1, y1 = y0 + 1, x1 = x0 + 1;

    // validity folded into weights (border-zero semantics)
    float Wz0 = ((unsigned)z0 < (unsigned)D) ? (1.0f - fz) : 0.0f;
    float Wz1 = ((unsigned)z1 < (unsigned)D) ? fz          : 0.0f;
    float Wy0 = ((unsigned)y0 < (unsigned)H) ? (1.0f - fy) : 0.0f;
    float Wy1 = ((unsigned)y1 < (unsigned)H) ? fy          : 0.0f;
    float Wx0 = ((unsigned)x0 < (unsigned)W) ? (1.0f - fx) : 0.0f;
    float Wx1 = ((unsigned)x1 < (unsigned)W) ? fx          : 0.0f;

    int zc0 = min(max(z0, 0), D - 1), zc1 = min(max(z1, 0), D - 1);
    int yc0 = min(max(y0, 0), H - 1), yc1 = min(max(y1, 0), H - 1);
    int xc0 = min(max(x0, 0), W - 1), xc1 = min(max(x1, 0), W - 1);

    // this lane's x column + x weight
    int   xc = sub ? xc1 : xc0;
    float wx = sub ? Wx1 : Wx0;

    int r00 = (zc0 * H + yc0) * W + xc;   // (z0,y0)
    int r01 = (zc0 * H + yc1) * W + xc;   // (z0,y1)
    int r10 = (zc1 * H + yc0) * W + xc;   // (z1,y0)
    int r11 = (zc1 * H + yc1) * W + xc;   // (z1,y1)

    // 4 corner gathers; pair lanes hit adjacent float4s -> shared wavefront
    float4 c00 = in[r00];
    float4 c01 = in[r01];
    float4 c10 = in[r10];
    float4 c11 = in[r11];

    // per-channel z/y blend, then x weight; reduce across the lane pair
    float px, py, pz;
    {
        float a0 = fmaf(c01.x, Wy1, c00.x * Wy0);
        float a1 = fmaf(c11.x, Wy1, c10.x * Wy0);
        px = wx * fmaf(a1, Wz1, a0 * Wz0);
    }
    {
        float a0 = fmaf(c01.y, Wy1, c00.y * Wy0);
        float a1 = fmaf(c11.y, Wy1, c10.y * Wy0);
        py = wx * fmaf(a1, Wz1, a0 * Wz0);
    }
    {
        float a0 = fmaf(c01.z, Wy1, c00.z * Wy0);
        float a1 = fmaf(c11.z, Wy1, c10.z * Wy0);
        pz = wx * fmaf(a1, Wz1, a0 * Wz0);
    }
    px += __shfl_xor_sync(0xFFFFFFFFu, px, 1);
    py += __shfl_xor_sync(0xFFFFFFFFu, py, 1);
    pz += __shfl_xor_sync(0xFFFFFFFFu, pz, 1);

    if (sub == 0) {
        if (!LAST) {
            float4 r;
            r.x = v.x + px;
            r.y = v.y + py;
            r.z = v.z + pz;
            r.w = 0.0f;
            out4[idx] = r;
        } else {
            out_soa[idx]            = (v.x + px) * (1.0f / (0.5f * (D - 1)));
            out_soa[idx + NVOX]     = (v.y + py) * (1.0f / (0.5f * (H - 1)));
            out_soa[idx + 2 * NVOX] = (v.z + pz) * (1.0f / (0.5f * (W - 1)));
        }
    }
}

extern "C" void kernel_launch(void* const* d_in, const int* in_sizes, int n_in,
                              void* d_out, int out_size)
{
    const float* vec = (const float*)d_in[0];
    float* out = (float*)d_out;

    float4 *bufA, *bufB;
    cudaGetSymbolAddress((void**)&bufA, g_bufA);
    cudaGetSymbolAddress((void**)&bufB, g_bufB);

    const int threads = 256;
    const int blocks_scale = NVOX / threads;          // 19200, exact
    const int blocks_int   = (2 * NVOX) / threads;    // 38400, exact

    scale_in_kernel<<<blocks_scale, threads>>>(vec, bufA);

    float4* cur = bufA;
    float4* nxt = bufB;
    for (int i = 0; i < NSTEPS - 1; ++i) {
        integrate_kernel<false><<<blocks_int, threads>>>(cur, nxt, nullptr);
        float4* tmp = cur; cur = nxt; nxt = tmp;
    }
    integrate_kernel<true><<<blocks_int, threads>>>(cur, nullptr, out);
}